// round 13
// baseline (speedup 1.0000x reference)
#include <cuda_runtime.h>
#include <cuda_fp16.h>
#include <cstdint>

// Problem constants
constexpr int NN = 100000;   // nodes
constexpr int NE = 1600000;  // edges
constexpr int NF = 128;      // input feats
constexpr int NC = 40;       // classes (post-projection feature width)
constexpr int SLOT = 64;     // fixed per-node CSR slot (max deg ~36 for Poisson(16))

// ---------------- scratch (static device globals; no allocation) -------------
__device__ __align__(256) float  d_invdeg[NN];
__device__ __align__(256) float  d_dis[NN];
__device__ __align__(256) int    d_cur[NN];
__device__ __align__(256) int2   d_edat[(size_t)NN * SLOT];  // (row, raw ew bits)
__device__ __align__(256) __half d_hA[(size_t)NN * NC];      // fp16 intermediates
__device__ __align__(256) __half d_hB[(size_t)NN * NC];

// ---------------- kernels ----------------------------------------------------

__global__ void init_kernel() {
    int i = blockIdx.x * blockDim.x + threadIdx.x;
    if (i < NN) d_cur[i] = i * SLOT;
}

// fixed-slot CSR fill: append (row, raw ew). No counting pass, no scan.
__global__ void fill_kernel(const int* __restrict__ row,
                            const int* __restrict__ col,
                            const float* __restrict__ ew) {
    int e = blockIdx.x * blockDim.x + threadIdx.x;
    if (e < NE) {
        int r = row[e];
        int c = col[e];
        if (r >= 0 && r < NN && c >= 0 && c < NN) {
            int pos = atomicAdd(&d_cur[c], 1);
            if (pos < (c + 1) * SLOT)              // overflow guard (P ~ 1e-20)
                d_edat[pos] = make_int2(r, __float_as_int(ew[e]));
        }
    }
}

// weighted degree from each node's contiguous slot; derive invdeg and dis.
__global__ void degsum_kernel() {
    int i = blockIdx.x * blockDim.x + threadIdx.x;
    if (i >= NN) return;
    int s = i * SLOT;
    int e = d_cur[i];
    if (e > s + SLOT) e = s + SLOT;
    float deg = 0.0f;
    for (int j = s; j < e; j++)
        deg += __int_as_float(d_edat[j].y);
    bool pos = (deg > 0.0f);
    d_invdeg[i] = pos ? (1.0f / deg) : 0.0f;
    d_dis[i]    = pos ? rsqrtf(deg) : 0.0f;
}

// g0[NN,40] = fp16( dis * (x[NN,128] @ W[128,40]) )
// Vectorized-LDS inner loop: per k, 1x LDS.128 (hv) + 1x LDS.128 + 1x LDS.32
// (wv, warp-broadcast) feeding 20 FMA. sW padded so each 5-class group is
// 32B-aligned; sh padded so each 4-node group is 16B-aligned.
__global__ void __launch_bounds__(128) xw_kernel(
        const float* __restrict__ x,
        const float* __restrict__ W,
        __half* __restrict__ y) {
    __shared__ float sWp[NF][64];    // [k][cg*8 + j], 32 KB, rows 256B
    __shared__ float sh[32][68];     // [k][node], 8.7 KB, rows 272B
    int t = threadIdx.x;
    int nb = blockIdx.x * 64;

    // load W into padded layout
    for (int i = t; i < NF * NC; i += 128) {
        int k = i / NC, c = i % NC;
        sWp[k][(c / 5) * 8 + (c % 5)] = W[i];
    }

    int ng = t & 15;    // 16 node-groups x 4 nodes
    int cg = t >> 4;    // 8 class-groups x 5 classes
    float acc[4][5] = {};

    for (int kc = 0; kc < NF; kc += 32) {
        __syncthreads();
        for (int i = t; i < 64 * 32; i += 128) {
            int n = i >> 5, k = i & 31;
            int node = nb + n;
            sh[k][n] = (node < NN) ? x[(size_t)node * NF + kc + k] : 0.0f;
        }
        __syncthreads();
        #pragma unroll 8
        for (int k = 0; k < 32; k++) {
            float4 hv  = *reinterpret_cast<const float4*>(&sh[k][ng * 4]);
            float4 wv4 = *reinterpret_cast<const float4*>(&sWp[kc + k][cg * 8]);
            float  wv5 = sWp[kc + k][cg * 8 + 4];
            const float h[4] = {hv.x, hv.y, hv.z, hv.w};
            #pragma unroll
            for (int i = 0; i < 4; i++) {
                acc[i][0] += h[i] * wv4.x;
                acc[i][1] += h[i] * wv4.y;
                acc[i][2] += h[i] * wv4.z;
                acc[i][3] += h[i] * wv4.w;
                acc[i][4] += h[i] * wv5;
            }
        }
    }
    #pragma unroll
    for (int i = 0; i < 4; i++) {
        int node = nb + ng * 4 + i;
        if (node < NN) {
            float sd = d_dis[node];   // g0 = D^{-1/2}(xW)
            #pragma unroll
            for (int j = 0; j < 5; j++)
                y[(size_t)node * NC + cg * 5 + j] = __float2half(acc[i][j] * sd);
        }
    }
}

// Pull hop in g-space, fp16 -> fp16: g_next[c] = invdeg[c] * sum(ew * g[row]).
// 5-lane group per node (40 halves = 5 uint4), 6 nodes/warp, unroll-4 MLP.
__global__ void hop_h2h(const __half* __restrict__ hin,
                        __half* __restrict__ hout) {
    int gwarp = (blockIdx.x * blockDim.x + threadIdx.x) >> 5;
    int ln = threadIdx.x & 31;
    if (ln >= 30) return;
    int node = gwarp * 6 + ln / 5;
    if (node >= NN) return;
    int sub = ln % 5;

    int s = node * SLOT;
    int e = d_cur[node];
    if (e > s + SLOT) e = s + SLOT;

    float acc[8] = {};
    int i = s;
    for (; i + 4 <= e; i += 4) {
        int2 ed[4];
        uint4 v[4];
        #pragma unroll
        for (int u = 0; u < 4; u++) ed[u] = d_edat[i + u];
        #pragma unroll
        for (int u = 0; u < 4; u++)
            v[u] = __ldg(reinterpret_cast<const uint4*>(hin + (size_t)ed[u].x * NC) + sub);
        #pragma unroll
        for (int u = 0; u < 4; u++) {
            float w = __int_as_float(ed[u].y);
            const unsigned* p = &v[u].x;
            #pragma unroll
            for (int q = 0; q < 4; q++) {
                float2 f = __half22float2(*reinterpret_cast<const __half2*>(&p[q]));
                acc[2*q]   += f.x * w;
                acc[2*q+1] += f.y * w;
            }
        }
    }
    for (; i < e; i++) {
        int2 e0 = d_edat[i];
        float w = __int_as_float(e0.y);
        uint4 v0 = __ldg(reinterpret_cast<const uint4*>(hin + (size_t)e0.x * NC) + sub);
        const unsigned* p = &v0.x;
        #pragma unroll
        for (int q = 0; q < 4; q++) {
            float2 f = __half22float2(*reinterpret_cast<const __half2*>(&p[q]));
            acc[2*q]   += f.x * w;
            acc[2*q+1] += f.y * w;
        }
    }
    float idg = d_invdeg[node];      // destination-side D^{-1}
    uint4 o;
    unsigned* po = &o.x;
    #pragma unroll
    for (int q = 0; q < 4; q++) {
        __half2 h = __floats2half2_rn(acc[2*q] * idg, acc[2*q+1] * idg);
        po[q] = *reinterpret_cast<unsigned*>(&h);
    }
    *(reinterpret_cast<uint4*>(hout + (size_t)node * NC) + sub) = o;
}

// Final hop, fp16 -> fp32 d_out: out[c] = dis[c] * sum(ew * g[row]).
__global__ void hop_h2f(const __half* __restrict__ hin,
                        float* __restrict__ hout) {
    int gwarp = (blockIdx.x * blockDim.x + threadIdx.x) >> 5;
    int ln = threadIdx.x & 31;
    if (ln >= 30) return;
    int node = gwarp * 6 + ln / 5;
    if (node >= NN) return;
    int sub = ln % 5;

    int s = node * SLOT;
    int e = d_cur[node];
    if (e > s + SLOT) e = s + SLOT;

    float acc[8] = {};
    int i = s;
    for (; i + 4 <= e; i += 4) {
        int2 ed[4];
        uint4 v[4];
        #pragma unroll
        for (int u = 0; u < 4; u++) ed[u] = d_edat[i + u];
        #pragma unroll
        for (int u = 0; u < 4; u++)
            v[u] = __ldg(reinterpret_cast<const uint4*>(hin + (size_t)ed[u].x * NC) + sub);
        #pragma unroll
        for (int u = 0; u < 4; u++) {
            float w = __int_as_float(ed[u].y);
            const unsigned* p = &v[u].x;
            #pragma unroll
            for (int q = 0; q < 4; q++) {
                float2 f = __half22float2(*reinterpret_cast<const __half2*>(&p[q]));
                acc[2*q]   += f.x * w;
                acc[2*q+1] += f.y * w;
            }
        }
    }
    for (; i < e; i++) {
        int2 e0 = d_edat[i];
        float w = __int_as_float(e0.y);
        uint4 v0 = __ldg(reinterpret_cast<const uint4*>(hin + (size_t)e0.x * NC) + sub);
        const unsigned* p = &v0.x;
        #pragma unroll
        for (int q = 0; q < 4; q++) {
            float2 f = __half22float2(*reinterpret_cast<const __half2*>(&p[q]));
            acc[2*q]   += f.x * w;
            acc[2*q+1] += f.y * w;
        }
    }
    float dis = d_dis[node];         // out = D^{-1/2} A_w g2
    float4* dst = reinterpret_cast<float4*>(hout + (size_t)node * NC + sub * 8);
    dst[0] = make_float4(acc[0]*dis, acc[1]*dis, acc[2]*dis, acc[3]*dis);
    dst[1] = make_float4(acc[4]*dis, acc[5]*dis, acc[6]*dis, acc[7]*dis);
}

// ---------------- launch ------------------------------------------------------

extern "C" void kernel_launch(void* const* d_in, const int* in_sizes, int n_in,
                              void* d_out, int out_size) {
    // Resolve inputs BY ELEMENT COUNT (order-independent; all counts distinct)
    const float* x  = nullptr;
    const int*   ei = nullptr;
    const float* ew = nullptr;
    const float* W  = nullptr;
    for (int i = 0; i < n_in; i++) {
        long long sz = in_sizes[i];
        if      (sz == (long long)NN * NF) x  = (const float*)d_in[i];
        else if (sz == (long long)2 * NE)  ei = (const int*)d_in[i];
        else if (sz == (long long)NE)      ew = (const float*)d_in[i];
        else if (sz == (long long)NF * NC) W  = (const float*)d_in[i];
    }
    float* out = (float*)d_out;

    const int* row = ei;        // edge_index[0, :]
    const int* col = ei + NE;   // edge_index[1, :]

    __half* hA; cudaGetSymbolAddress((void**)&hA, d_hA);
    __half* hB; cudaGetSymbolAddress((void**)&hB, d_hB);

    // --- prep: cursor init -> fixed-slot fill -> weighted degree ---
    init_kernel<<<(NN + 255)/256, 256>>>();
    fill_kernel<<<(NE + 255)/256, 256>>>(row, col, ew);
    degsum_kernel<<<(NN + 255)/256, 256>>>();

    // --- project + prescale: g0 = fp16(dis * (x @ W)) ---
    xw_kernel<<<(NN + 63)/64, 128>>>(x, W, hA);

    // --- three pull hops in g-space (6 nodes/warp, 5-lane groups) ---
    const int WARPS = (NN + 5) / 6;
    const int HOP_BLOCKS = (WARPS * 32 + 255) / 256;
    hop_h2h<<<HOP_BLOCKS, 256>>>(hA, hB);
    hop_h2h<<<HOP_BLOCKS, 256>>>(hB, hA);
    hop_h2f<<<HOP_BLOCKS, 256>>>(hA, out);
}

// round 14
// speedup vs baseline: 1.1745x; 1.1745x over previous
#include <cuda_runtime.h>
#include <cuda_fp16.h>
#include <mma.h>
#include <cstdint>

using namespace nvcuda;

// Problem constants
constexpr int NN = 100000;   // nodes
constexpr int NE = 1600000;  // edges
constexpr int NF = 128;      // input feats
constexpr int NC = 40;       // classes (post-projection feature width)
constexpr int NCP = 48;      // NC padded to 3x16 for wmma
constexpr int SLOT = 64;     // fixed per-node CSR slot (max deg ~36 for Poisson(16))

// ---------------- scratch (static device globals; no allocation) -------------
__device__ __align__(256) float  d_invdeg[NN];
__device__ __align__(256) float  d_dis[NN];
__device__ __align__(256) int    d_cur[NN];
__device__ __align__(256) int2   d_edat[(size_t)NN * SLOT];  // (row, raw ew bits)
__device__ __align__(256) __half d_Wh[NF * NCP];             // fp16 W, N-padded
__device__ __align__(256) __half d_hA[(size_t)NN * NC];      // fp16 intermediates
__device__ __align__(256) __half d_hB[(size_t)NN * NC];

// ---------------- kernels ----------------------------------------------------

__global__ void init_kernel() {
    int i = blockIdx.x * blockDim.x + threadIdx.x;
    if (i < NN) d_cur[i] = i * SLOT;
}

// convert W[128,40] fp32 -> d_Wh[128,48] fp16 (zero-padded cols)
__global__ void wconv_kernel(const float* __restrict__ W) {
    int i = blockIdx.x * blockDim.x + threadIdx.x;
    if (i < NF * NCP) {
        int k = i / NCP, c = i % NCP;
        d_Wh[i] = __float2half((c < NC) ? W[k * NC + c] : 0.0f);
    }
}

// fixed-slot CSR fill: append (row, raw ew). No counting pass, no scan.
__global__ void fill_kernel(const int* __restrict__ row,
                            const int* __restrict__ col,
                            const float* __restrict__ ew) {
    int e = blockIdx.x * blockDim.x + threadIdx.x;
    if (e < NE) {
        int r = row[e];
        int c = col[e];
        if (r >= 0 && r < NN && c >= 0 && c < NN) {
            int pos = atomicAdd(&d_cur[c], 1);
            if (pos < (c + 1) * SLOT)              // overflow guard (P ~ 1e-20)
                d_edat[pos] = make_int2(r, __float_as_int(ew[e]));
        }
    }
}

// weighted degree from each node's contiguous slot; derive invdeg and dis.
__global__ void degsum_kernel() {
    int i = blockIdx.x * blockDim.x + threadIdx.x;
    if (i >= NN) return;
    int s = i * SLOT;
    int e = d_cur[i];
    if (e > s + SLOT) e = s + SLOT;
    float deg = 0.0f;
    for (int j = s; j < e; j++)
        deg += __int_as_float(d_edat[j].y);
    bool pos = (deg > 0.0f);
    d_invdeg[i] = pos ? (1.0f / deg) : 0.0f;
    d_dis[i]    = pos ? rsqrtf(deg) : 0.0f;
}

// g0[NN,40] = fp16( dis * (x[NN,128] @ W[128,40]) )  via tensor cores.
// Block: 128 threads / 4 warps, 64 nodes. Warp w: rows 16w..16w+15, all 48 cols
// (3 m16n16k16 fragments, fp16 in / fp32 accumulate).
__global__ void __launch_bounds__(128) xw_wmma(const float* __restrict__ x,
                                               __half* __restrict__ y) {
    __shared__ __half sx[64][136];   // x tile, fp16, ldm=136 (mult of 8)
    __shared__ __half sw[NF][NCP];   // W, fp16
    __shared__ float  sc[64][NCP];   // fp32 epilogue buffer
    int t = threadIdx.x;
    int warp = t >> 5;
    int nb = blockIdx.x * 64;

    // stage W (6144 halves = 3072 half2)
    for (int i = t; i < NF * NCP / 2; i += 128)
        reinterpret_cast<__half2*>(&sw[0][0])[i] =
            reinterpret_cast<const __half2*>(d_Wh)[i];

    // stage x tile: 64 rows x 32 float4, convert fp32->fp16
    for (int i = t; i < 64 * 32; i += 128) {
        int n = i >> 5, c4 = i & 31;
        int node = nb + n;
        float4 v = (node < NN)
                 ? reinterpret_cast<const float4*>(x + (size_t)node * NF)[c4]
                 : make_float4(0.f, 0.f, 0.f, 0.f);
        *reinterpret_cast<__half2*>(&sx[n][c4 * 4])     = __floats2half2_rn(v.x, v.y);
        *reinterpret_cast<__half2*>(&sx[n][c4 * 4 + 2]) = __floats2half2_rn(v.z, v.w);
    }
    __syncthreads();

    wmma::fragment<wmma::accumulator, 16, 16, 16, float> acc[3];
    #pragma unroll
    for (int j = 0; j < 3; j++) wmma::fill_fragment(acc[j], 0.0f);

    #pragma unroll
    for (int k = 0; k < NF / 16; k++) {
        wmma::fragment<wmma::matrix_a, 16, 16, 16, __half, wmma::row_major> a;
        wmma::load_matrix_sync(a, &sx[warp * 16][k * 16], 136);
        #pragma unroll
        for (int j = 0; j < 3; j++) {
            wmma::fragment<wmma::matrix_b, 16, 16, 16, __half, wmma::row_major> b;
            wmma::load_matrix_sync(b, &sw[k * 16][j * 16], NCP);
            wmma::mma_sync(acc[j], a, b, acc[j]);
        }
    }
    #pragma unroll
    for (int j = 0; j < 3; j++)
        wmma::store_matrix_sync(&sc[warp * 16][j * 16], acc[j], NCP,
                                wmma::mem_row_major);
    __syncthreads();

    // epilogue: scale by dis, emit fp16, 40 of 48 cols (20 half2 per node)
    for (int i = t; i < 64 * 20; i += 128) {
        int n = i / 20, c2 = i % 20;
        int node = nb + n;
        if (node < NN) {
            float sd = d_dis[node];   // g0 = D^{-1/2}(xW)
            __half2 h = __floats2half2_rn(sc[n][c2 * 2] * sd,
                                          sc[n][c2 * 2 + 1] * sd);
            reinterpret_cast<__half2*>(y + (size_t)node * NC)[c2] = h;
        }
    }
}

// Pull hop in g-space, fp16 -> fp16: g_next[c] = invdeg[c] * sum(ew * g[row]).
// 5-lane group per node (40 halves = 5 uint4), 6 nodes/warp, unroll-4 MLP.
__global__ void hop_h2h(const __half* __restrict__ hin,
                        __half* __restrict__ hout) {
    int gwarp = (blockIdx.x * blockDim.x + threadIdx.x) >> 5;
    int ln = threadIdx.x & 31;
    if (ln >= 30) return;
    int node = gwarp * 6 + ln / 5;
    if (node >= NN) return;
    int sub = ln % 5;

    int s = node * SLOT;
    int e = d_cur[node];
    if (e > s + SLOT) e = s + SLOT;

    float acc[8] = {};
    int i = s;
    for (; i + 4 <= e; i += 4) {
        int2 ed[4];
        uint4 v[4];
        #pragma unroll
        for (int u = 0; u < 4; u++) ed[u] = d_edat[i + u];
        #pragma unroll
        for (int u = 0; u < 4; u++)
            v[u] = __ldg(reinterpret_cast<const uint4*>(hin + (size_t)ed[u].x * NC) + sub);
        #pragma unroll
        for (int u = 0; u < 4; u++) {
            float w = __int_as_float(ed[u].y);
            const unsigned* p = &v[u].x;
            #pragma unroll
            for (int q = 0; q < 4; q++) {
                float2 f = __half22float2(*reinterpret_cast<const __half2*>(&p[q]));
                acc[2*q]   += f.x * w;
                acc[2*q+1] += f.y * w;
            }
        }
    }
    for (; i < e; i++) {
        int2 e0 = d_edat[i];
        float w = __int_as_float(e0.y);
        uint4 v0 = __ldg(reinterpret_cast<const uint4*>(hin + (size_t)e0.x * NC) + sub);
        const unsigned* p = &v0.x;
        #pragma unroll
        for (int q = 0; q < 4; q++) {
            float2 f = __half22float2(*reinterpret_cast<const __half2*>(&p[q]));
            acc[2*q]   += f.x * w;
            acc[2*q+1] += f.y * w;
        }
    }
    float idg = d_invdeg[node];      // destination-side D^{-1}
    uint4 o;
    unsigned* po = &o.x;
    #pragma unroll
    for (int q = 0; q < 4; q++) {
        __half2 h = __floats2half2_rn(acc[2*q] * idg, acc[2*q+1] * idg);
        po[q] = *reinterpret_cast<unsigned*>(&h);
    }
    *(reinterpret_cast<uint4*>(hout + (size_t)node * NC) + sub) = o;
}

// Final hop, fp16 -> fp32 d_out: out[c] = dis[c] * sum(ew * g[row]).
__global__ void hop_h2f(const __half* __restrict__ hin,
                        float* __restrict__ hout) {
    int gwarp = (blockIdx.x * blockDim.x + threadIdx.x) >> 5;
    int ln = threadIdx.x & 31;
    if (ln >= 30) return;
    int node = gwarp * 6 + ln / 5;
    if (node >= NN) return;
    int sub = ln % 5;

    int s = node * SLOT;
    int e = d_cur[node];
    if (e > s + SLOT) e = s + SLOT;

    float acc[8] = {};
    int i = s;
    for (; i + 4 <= e; i += 4) {
        int2 ed[4];
        uint4 v[4];
        #pragma unroll
        for (int u = 0; u < 4; u++) ed[u] = d_edat[i + u];
        #pragma unroll
        for (int u = 0; u < 4; u++)
            v[u] = __ldg(reinterpret_cast<const uint4*>(hin + (size_t)ed[u].x * NC) + sub);
        #pragma unroll
        for (int u = 0; u < 4; u++) {
            float w = __int_as_float(ed[u].y);
            const unsigned* p = &v[u].x;
            #pragma unroll
            for (int q = 0; q < 4; q++) {
                float2 f = __half22float2(*reinterpret_cast<const __half2*>(&p[q]));
                acc[2*q]   += f.x * w;
                acc[2*q+1] += f.y * w;
            }
        }
    }
    for (; i < e; i++) {
        int2 e0 = d_edat[i];
        float w = __int_as_float(e0.y);
        uint4 v0 = __ldg(reinterpret_cast<const uint4*>(hin + (size_t)e0.x * NC) + sub);
        const unsigned* p = &v0.x;
        #pragma unroll
        for (int q = 0; q < 4; q++) {
            float2 f = __half22float2(*reinterpret_cast<const __half2*>(&p[q]));
            acc[2*q]   += f.x * w;
            acc[2*q+1] += f.y * w;
        }
    }
    float dis = d_dis[node];         // out = D^{-1/2} A_w g2
    float4* dst = reinterpret_cast<float4*>(hout + (size_t)node * NC + sub * 8);
    dst[0] = make_float4(acc[0]*dis, acc[1]*dis, acc[2]*dis, acc[3]*dis);
    dst[1] = make_float4(acc[4]*dis, acc[5]*dis, acc[6]*dis, acc[7]*dis);
}

// ---------------- launch ------------------------------------------------------

extern "C" void kernel_launch(void* const* d_in, const int* in_sizes, int n_in,
                              void* d_out, int out_size) {
    // Resolve inputs BY ELEMENT COUNT (order-independent; all counts distinct)
    const float* x  = nullptr;
    const int*   ei = nullptr;
    const float* ew = nullptr;
    const float* W  = nullptr;
    for (int i = 0; i < n_in; i++) {
        long long sz = in_sizes[i];
        if      (sz == (long long)NN * NF) x  = (const float*)d_in[i];
        else if (sz == (long long)2 * NE)  ei = (const int*)d_in[i];
        else if (sz == (long long)NE)      ew = (const float*)d_in[i];
        else if (sz == (long long)NF * NC) W  = (const float*)d_in[i];
    }
    float* out = (float*)d_out;

    const int* row = ei;        // edge_index[0, :]
    const int* col = ei + NE;   // edge_index[1, :]

    __half* hA; cudaGetSymbolAddress((void**)&hA, d_hA);
    __half* hB; cudaGetSymbolAddress((void**)&hB, d_hB);

    // --- prep: cursor init -> W conversion -> fixed-slot fill -> degrees ---
    init_kernel<<<(NN + 255)/256, 256>>>();
    wconv_kernel<<<(NF * NCP + 255)/256, 256>>>(W);
    fill_kernel<<<(NE + 255)/256, 256>>>(row, col, ew);
    degsum_kernel<<<(NN + 255)/256, 256>>>();

    // --- project + prescale: g0 = fp16(dis * (x @ W)) on tensor cores ---
    xw_wmma<<<(NN + 63)/64, 128>>>(x, hA);

    // --- three pull hops in g-space (6 nodes/warp, 5-lane groups) ---
    const int WARPS = (NN + 5) / 6;
    const int HOP_BLOCKS = (WARPS * 32 + 255) / 256;
    hop_h2h<<<HOP_BLOCKS, 256>>>(hA, hB);
    hop_h2h<<<HOP_BLOCKS, 256>>>(hB, hA);
    hop_h2f<<<HOP_BLOCKS, 256>>>(hA, out);
}